// round 1
// baseline (speedup 1.0000x reference)
#include <cuda_runtime.h>
#include <cuda_bf16.h>
#include <cstdint>

// Problem shapes (fixed by setup_inputs): B=4, N=128, C_IN=C_OUT=32, X=3.
#define BZ 4
#define NN 128
#define CC 32

// ---------------------------------------------------------------------------
// Scratch (no allocations allowed -> __device__ globals)
// ---------------------------------------------------------------------------
// Per-(z,c) partial moments: [z][c][m][k], m in 0..15:
//   m=0: p0            = sum_d f
//   m=1..3: p1[x]      = sum_d geo[z,d,x] * f
//   m=4..6: gy[y]*p0
//   m=7..15: gy[y]*p1[x]  (index 7 + y*3 + x)
__device__ float g_partial[BZ][NN][16][CC];   // 1 MB
__device__ float g_M[BZ][16][CC];             // reduced moments
__device__ float g_W12[3][3][CC][CC];         // W12[y][x][i][k] = sum_j W2[y,i,j]*W1[x,j,k]
__device__ float g_U[BZ][512];                // U0[32] | U1[3*32] | U2[3*32] | U3[9*32]

// Robust scalar load: handles int32/int64-low-word or float32 encodings of n_norm.
__device__ __forceinline__ float load_scalar_f(const void* p) {
    int iv = *(const int*)p;
    int ex = (iv >> 23) & 0xFF;
    if (ex > 60 && ex < 200) return __int_as_float(iv);  // looks like a normal float
    return (float)iv;                                     // integer encoding
}

// ---------------------------------------------------------------------------
// K1a: per-(z,c) partial moments. grid = B*N blocks, 128 threads.
// ---------------------------------------------------------------------------
__global__ void k_partial(const float* __restrict__ feat, const float* __restrict__ geo) {
    int zc = blockIdx.x;
    int z = zc >> 7;
    int c = zc & (NN - 1);
    int t = threadIdx.x;          // 128
    int k = t & 31;
    int dgrp = t >> 5;            // 0..3

    const float* fbase = feat + ((size_t)zc << 12) + k;   // feat[z][c][d][k], d stride = 32
    const float* gz = geo + z * NN * 3;

    float s0 = 0.f, sx = 0.f, sy = 0.f, sz2 = 0.f;
    #pragma unroll 4
    for (int d = dgrp; d < NN; d += 4) {
        float f  = fbase[d * 32];
        float g0 = gz[d * 3 + 0];
        float g1 = gz[d * 3 + 1];
        float g2 = gz[d * 3 + 2];
        s0  += f;
        sx  = fmaf(f, g0, sx);
        sy  = fmaf(f, g1, sy);
        sz2 = fmaf(f, g2, sz2);
    }

    __shared__ float sm[4][4][32];   // [dgrp][comp][k]
    __shared__ float sgy[3];
    sm[dgrp][0][k] = s0;
    sm[dgrp][1][k] = sx;
    sm[dgrp][2][k] = sy;
    sm[dgrp][3][k] = sz2;
    if (t < 3) sgy[t] = geo[(z * NN + c) * 3 + t];
    __syncthreads();

    // Reduce 4 d-strips: thread (comp,k) sums its column into sm[0][comp][k].
    {
        int comp = t >> 5;
        float v = sm[0][comp][k] + sm[1][comp][k] + sm[2][comp][k] + sm[3][comp][k];
        __syncthreads();
        sm[0][comp][k] = v;
    }
    __syncthreads();

    float* outp = &g_partial[z][c][0][0];
    for (int m = (t >> 5); m < 16; m += 4) {
        float v;
        if (m == 0)      v = sm[0][0][k];
        else if (m < 4)  v = sm[0][m][k];
        else if (m < 7)  v = sgy[m - 4] * sm[0][0][k];
        else {
            int mm = m - 7;
            int yy = mm / 3, xx = mm - yy * 3;
            v = sgy[yy] * sm[0][1 + xx][k];
        }
        outp[m * 32 + k] = v;
    }
}

// ---------------------------------------------------------------------------
// K1b: reduce partials over c. grid = B, 512 threads (one per (m,k)).
// ---------------------------------------------------------------------------
__global__ void k_reduce() {
    int z = blockIdx.x;
    int t = threadIdx.x;  // 512
    const float* base = &g_partial[z][0][0][0];
    float s = 0.f;
    #pragma unroll 8
    for (int c = 0; c < NN; c++) s += base[c * 512 + t];
    (&g_M[z][0][0])[t] = s;
}

// ---------------------------------------------------------------------------
// K2a: W12[y,x,i,k] = sum_j W2[y,i,j]*W1[x,j,k]. grid = 9, 1024 threads.
// ---------------------------------------------------------------------------
__global__ void k_w12(const float* __restrict__ W1, const float* __restrict__ W2) {
    int yx = blockIdx.x;
    int y = yx / 3, x = yx - y * 3;
    int i = threadIdx.x >> 5;
    int k = threadIdx.x & 31;
    const float* w2r = W2 + (y * 32 + i) * 32;   // W2[y][i][j]
    const float* w1c = W1 + x * 32 * 32 + k;     // W1[x][j][k], j stride 32
    float s = 0.f;
    #pragma unroll
    for (int j = 0; j < 32; j++) s = fmaf(w2r[j], w1c[j * 32], s);
    g_W12[y][x][i][k] = s;
}

// ---------------------------------------------------------------------------
// K2b: per-z coefficients U. grid = B, 512 threads (one output each).
// ---------------------------------------------------------------------------
__global__ void k_coeff() {
    int z = blockIdx.x;
    int t = threadIdx.x;  // 512
    __shared__ float sM[16][32];
    (&sM[0][0])[t] = (&g_M[z][0][0])[t];
    __syncthreads();

    float r = 0.f;
    if (t < 32) {
        // U0[i] = sum_{y,x,k} W12[y,x,i,k] * M11[y,x,k]
        int i = t;
        for (int y = 0; y < 3; y++)
            for (int x = 0; x < 3; x++) {
                const float* w = &g_W12[y][x][i][0];
                const float* m = &sM[7 + y * 3 + x][0];
                #pragma unroll
                for (int k = 0; k < 32; k++) r = fmaf(w[k], m[k], r);
            }
    } else if (t < 128) {
        // U1[x,i] = sum_{y,k} W12[y,x,i,k] * M10[y,k]
        int x = (t - 32) >> 5, i = t & 31;
        for (int y = 0; y < 3; y++) {
            const float* w = &g_W12[y][x][i][0];
            const float* m = &sM[4 + y][0];
            #pragma unroll
            for (int k = 0; k < 32; k++) r = fmaf(w[k], m[k], r);
        }
    } else if (t < 224) {
        // U2[y,i] = sum_{x,k} W12[y,x,i,k] * M01[x,k]
        int y = (t - 128) >> 5, i = t & 31;
        for (int x = 0; x < 3; x++) {
            const float* w = &g_W12[y][x][i][0];
            const float* m = &sM[1 + x][0];
            #pragma unroll
            for (int k = 0; k < 32; k++) r = fmaf(w[k], m[k], r);
        }
    } else {
        // U3[y,x,i] = sum_k W12[y,x,i,k] * M00[k]
        int m3 = t - 224;               // 0..287
        int yx = m3 >> 5, i = m3 & 31;
        int y = yx / 3, x = yx - y * 3;
        const float* w = &g_W12[y][x][i][0];
        const float* m = &sM[0][0];
        #pragma unroll
        for (int k = 0; k < 32; k++) r = fmaf(w[k], m[k], r);
    }
    g_U[z][t] = r;
}

// ---------------------------------------------------------------------------
// K3: output expansion. grid = B*N (one block per (z,a)), 256 threads.
// out[z,a,b,i] = inv_n * ( V0[i] + sum_x gb_x * V1[x,i] )
//   V0[i]   = U0[i] - ga . U2[:,i]
//   V1[x,i] = -U1[x,i] + sum_y ga_y * U3[y,x,i]
// ---------------------------------------------------------------------------
__global__ void k_expand(const float* __restrict__ geo, float* __restrict__ out,
                         const void* __restrict__ n_norm_ptr) {
    int za = blockIdx.x;
    int z = za >> 7;
    int a = za & (NN - 1);
    int t = threadIdx.x;  // 256

    __shared__ float sU[512];
    __shared__ float sg[NN * 3];
    __shared__ float V0[32];
    __shared__ float V1[3][32];

    sU[t] = g_U[z][t];
    sU[t + 256] = g_U[z][t + 256];
    for (int idx = t; idx < NN * 3; idx += 256) sg[idx] = geo[z * NN * 3 + idx];
    __syncthreads();

    float ga0 = sg[a * 3 + 0], ga1 = sg[a * 3 + 1], ga2 = sg[a * 3 + 2];

    if (t < 32) {
        int i = t;
        V0[i] = sU[i] - (ga0 * sU[128 + i] + ga1 * sU[160 + i] + ga2 * sU[192 + i]);
    } else if (t < 128) {
        int x = (t - 32) >> 5, i = t & 31;
        V1[x][i] = -sU[32 + x * 32 + i]
                 + ga0 * sU[224 + (0 * 3 + x) * 32 + i]
                 + ga1 * sU[224 + (1 * 3 + x) * 32 + i]
                 + ga2 * sU[224 + (2 * 3 + x) * 32 + i];
    }
    __syncthreads();

    float inv_n = 1.0f / load_scalar_f(n_norm_ptr);

    int i = t & 31;
    int bgrp = t >> 5;  // 0..7
    float v0  = V0[i];
    float v10 = V1[0][i], v11 = V1[1][i], v12 = V1[2][i];

    float* ob = out + (size_t)za * NN * 32;
    #pragma unroll 4
    for (int b = bgrp; b < NN; b += 8) {
        float gb0 = sg[b * 3 + 0], gb1 = sg[b * 3 + 1], gb2 = sg[b * 3 + 2];
        float v = fmaf(gb2, v12, fmaf(gb1, v11, fmaf(gb0, v10, v0)));
        ob[b * 32 + i] = inv_n * v;
    }
}

// ---------------------------------------------------------------------------
// kernel_launch
// Inputs (metadata order): features f32[4,128,128,32], geometry f32[4,128,3],
//                          W1 f32[3,32,32], W2 f32[3,32,32], n_norm scalar.
// Output: f32[4,128,128,32].
// ---------------------------------------------------------------------------
extern "C" void kernel_launch(void* const* d_in, const int* in_sizes, int n_in,
                              void* d_out, int out_size) {
    const float* feat = (const float*)d_in[0];
    const float* geo  = (const float*)d_in[1];
    const float* W1   = (const float*)d_in[2];
    const float* W2   = (const float*)d_in[3];
    const void*  nrm  = (n_in > 4) ? d_in[4] : nullptr;
    float* out = (float*)d_out;

    k_partial<<<BZ * NN, 128>>>(feat, geo);
    k_reduce<<<BZ, 512>>>();
    k_w12<<<9, 1024>>>(W1, W2);
    k_coeff<<<BZ, 512>>>();
    k_expand<<<BZ * NN, 256>>>(geo, out, nrm);
}

// round 4
// speedup vs baseline: 1.2311x; 1.2311x over previous
#include <cuda_runtime.h>
#include <cuda_bf16.h>
#include <cstdint>

// Problem shapes (fixed by setup_inputs): B=4, N=128, C_IN=C_OUT=32, X=3.
#define BZ 4
#define NN 128
#define CC 32

// ---------------------------------------------------------------------------
// Scratch (no allocations allowed -> __device__ globals)
// ---------------------------------------------------------------------------
// Per-(z,c) partial moments: [z][c][m][k], m in 0..15:
//   m=0: p0            = sum_d f
//   m=1..3: p1[x]      = sum_d geo[z,d,x] * f
//   m=4..6: gy[y]*p0
//   m=7..15: gy[y]*p1[x]  (index 7 + y*3 + x)
__device__ float g_partial[BZ][NN][16][CC];   // 1 MB
__device__ float g_U[BZ][512];                // U0[32] | U1[3*32] | U2[3*32] | U3[9*32]

// Robust scalar load: handles int32/int64-low-word or float32 encodings of n_norm.
__device__ __forceinline__ float load_scalar_f(const void* p) {
    int iv = *(const int*)p;
    int ex = (iv >> 23) & 0xFF;
    if (ex > 60 && ex < 200) return __int_as_float(iv);  // looks like a normal float
    return (float)iv;                                     // integer encoding
}

// ---------------------------------------------------------------------------
// K1: per-(z,c) partial moments. grid = B*N blocks, 128 threads.
// ---------------------------------------------------------------------------
__global__ void __launch_bounds__(128) k_partial(const float* __restrict__ feat,
                                                 const float* __restrict__ geo) {
    int zc = blockIdx.x;
    int z = zc >> 7;
    int c = zc & (NN - 1);
    int t = threadIdx.x;          // 128
    int k = t & 31;
    int dgrp = t >> 5;            // 0..3

    const float* fbase = feat + ((size_t)zc << 12) + k;   // feat[z][c][d][k], d stride = 32
    const float* gz = geo + z * NN * 3;

    float s0 = 0.f, sx = 0.f, sy = 0.f, sz2 = 0.f;
    #pragma unroll 4
    for (int d = dgrp; d < NN; d += 4) {
        float f  = fbase[d * 32];
        float g0 = gz[d * 3 + 0];
        float g1 = gz[d * 3 + 1];
        float g2 = gz[d * 3 + 2];
        s0  += f;
        sx  = fmaf(f, g0, sx);
        sy  = fmaf(f, g1, sy);
        sz2 = fmaf(f, g2, sz2);
    }

    __shared__ float sm[4][4][32];   // [dgrp][comp][k]
    __shared__ float sgy[3];
    sm[dgrp][0][k] = s0;
    sm[dgrp][1][k] = sx;
    sm[dgrp][2][k] = sy;
    sm[dgrp][3][k] = sz2;
    if (t < 3) sgy[t] = geo[(z * NN + c) * 3 + t];
    __syncthreads();

    // Reduce 4 d-strips: thread (comp,k) sums its column into sm[0][comp][k].
    {
        int comp = t >> 5;
        float v = sm[0][comp][k] + sm[1][comp][k] + sm[2][comp][k] + sm[3][comp][k];
        __syncthreads();
        sm[0][comp][k] = v;
    }
    __syncthreads();

    float* outp = &g_partial[z][c][0][0];
    for (int m = (t >> 5); m < 16; m += 4) {
        float v;
        if (m == 0)      v = sm[0][0][k];
        else if (m < 4)  v = sm[0][m][k];
        else if (m < 7)  v = sgy[m - 4] * sm[0][0][k];
        else {
            int mm = m - 7;
            int yy = mm / 3, xx = mm - yy * 3;
            v = sgy[yy] * sm[0][1 + xx][k];
        }
        outp[m * 32 + k] = v;
    }
}

// ---------------------------------------------------------------------------
// K2 (fused middle): per-z block does
//   (1) reduce g_partial over c -> sM[16][32]   (shared)
//   (2) W12[y,x,i,k] = sum_j W2[y,i,j]*W1[x,j,k] -> shared (36 KB)
//   (3) U coefficients from shared
// grid = B, 512 threads. __launch_bounds__ caps regs so launch succeeds.
// ---------------------------------------------------------------------------
__global__ void __launch_bounds__(512, 1) k_middle(const float* __restrict__ W1,
                                                   const float* __restrict__ W2) {
    int z = blockIdx.x;
    int t = threadIdx.x;  // 512

    __shared__ float sW12[9 * 32 * 32];  // 36 KB: [yx][i][k]
    __shared__ float sM[16][32];         // 2 KB

    // (1) reduce partials over c: each thread owns one (m,k) slot.
    {
        const float* base = &g_partial[z][0][0][0];
        float s = 0.f;
        #pragma unroll 8
        for (int c = 0; c < NN; c++) s += base[c * 512 + t];
        (&sM[0][0])[t] = s;
    }

    // (2) W12 into shared: 9216 outputs, 18 per thread.
    // Outer loop NOT unrolled -> keeps register pressure bounded.
    for (int r = 0; r < 18; r++) {
        int idx = t + r * 512;
        int yx = idx >> 10;                  // 0..8
        int i  = (idx >> 5) & 31;
        int k  = idx & 31;
        int y = yx / 3, x = yx - y * 3;
        const float* w2r = W2 + (y * 32 + i) * 32;   // W2[y][i][j]
        const float* w1c = W1 + x * 1024 + k;        // W1[x][j][k], j stride 32
        float acc = 0.f;
        #pragma unroll
        for (int j = 0; j < 32; j++) acc = fmaf(w2r[j], w1c[j * 32], acc);
        sW12[idx] = acc;
    }
    __syncthreads();

    // (3) U from shared. One output per thread.
    float r = 0.f;
    if (t < 32) {
        // U0[i] = sum_{y,x,k} W12[y,x,i,k] * M11[y,x,k]
        int i = t;
        for (int yx = 0; yx < 9; yx++) {
            const float* w = &sW12[(yx * 32 + i) * 32];
            const float* m = &sM[7 + yx][0];
            #pragma unroll
            for (int k = 0; k < 32; k++) r = fmaf(w[k], m[k], r);
        }
    } else if (t < 128) {
        // U1[x,i] = sum_{y,k} W12[y,x,i,k] * M10[y,k]
        int x = (t - 32) >> 5, i = t & 31;
        for (int y = 0; y < 3; y++) {
            const float* w = &sW12[((y * 3 + x) * 32 + i) * 32];
            const float* m = &sM[4 + y][0];
            #pragma unroll
            for (int k = 0; k < 32; k++) r = fmaf(w[k], m[k], r);
        }
    } else if (t < 224) {
        // U2[y,i] = sum_{x,k} W12[y,x,i,k] * M01[x,k]
        int y = (t - 128) >> 5, i = t & 31;
        for (int x = 0; x < 3; x++) {
            const float* w = &sW12[((y * 3 + x) * 32 + i) * 32];
            const float* m = &sM[1 + x][0];
            #pragma unroll
            for (int k = 0; k < 32; k++) r = fmaf(w[k], m[k], r);
        }
    } else {
        // U3[y,x,i] = sum_k W12[y,x,i,k] * M00[k]
        int m3 = t - 224;               // 0..287
        int yx = m3 >> 5, i = m3 & 31;
        const float* w = &sW12[(yx * 32 + i) * 32];
        const float* m = &sM[0][0];
        #pragma unroll
        for (int k = 0; k < 32; k++) r = fmaf(w[k], m[k], r);
    }
    g_U[z][t] = r;
}

// ---------------------------------------------------------------------------
// K3: output expansion. grid = B*N (one block per (z,a)), 256 threads.
// out[z,a,b,i] = inv_n * ( V0[i] + sum_x gb_x * V1[x,i] )
//   V0[i]   = U0[i] - ga . U2[:,i]
//   V1[x,i] = -U1[x,i] + sum_y ga_y * U3[y,x,i]
// ---------------------------------------------------------------------------
__global__ void __launch_bounds__(256) k_expand(const float* __restrict__ geo,
                                                float* __restrict__ out,
                                                const void* __restrict__ n_norm_ptr) {
    int za = blockIdx.x;
    int z = za >> 7;
    int a = za & (NN - 1);
    int t = threadIdx.x;  // 256

    __shared__ float sU[512];
    __shared__ float sg[NN * 3];
    __shared__ float V0[32];
    __shared__ float V1[3][32];

    sU[t] = g_U[z][t];
    sU[t + 256] = g_U[z][t + 256];
    for (int idx = t; idx < NN * 3; idx += 256) sg[idx] = geo[z * NN * 3 + idx];
    __syncthreads();

    float ga0 = sg[a * 3 + 0], ga1 = sg[a * 3 + 1], ga2 = sg[a * 3 + 2];

    if (t < 32) {
        int i = t;
        V0[i] = sU[i] - (ga0 * sU[128 + i] + ga1 * sU[160 + i] + ga2 * sU[192 + i]);
    } else if (t < 128) {
        int x = (t - 32) >> 5, i = t & 31;
        V1[x][i] = -sU[32 + x * 32 + i]
                 + ga0 * sU[224 + (0 * 3 + x) * 32 + i]
                 + ga1 * sU[224 + (1 * 3 + x) * 32 + i]
                 + ga2 * sU[224 + (2 * 3 + x) * 32 + i];
    }
    __syncthreads();

    float inv_n = 1.0f / load_scalar_f(n_norm_ptr);

    int i = t & 31;
    int bgrp = t >> 5;  // 0..7
    float v0  = V0[i];
    float v10 = V1[0][i], v11 = V1[1][i], v12 = V1[2][i];

    float* ob = out + (size_t)za * NN * 32;
    #pragma unroll 4
    for (int b = bgrp; b < NN; b += 8) {
        float gb0 = sg[b * 3 + 0], gb1 = sg[b * 3 + 1], gb2 = sg[b * 3 + 2];
        float v = fmaf(gb2, v12, fmaf(gb1, v11, fmaf(gb0, v10, v0)));
        ob[b * 32 + i] = inv_n * v;
    }
}

// ---------------------------------------------------------------------------
// kernel_launch
// Inputs (metadata order): features f32[4,128,128,32], geometry f32[4,128,3],
//                          W1 f32[3,32,32], W2 f32[3,32,32], n_norm scalar.
// Output: f32[4,128,128,32].
// ---------------------------------------------------------------------------
extern "C" void kernel_launch(void* const* d_in, const int* in_sizes, int n_in,
                              void* d_out, int out_size) {
    const float* feat = (const float*)d_in[0];
    const float* geo  = (const float*)d_in[1];
    const float* W1   = (const float*)d_in[2];
    const float* W2   = (const float*)d_in[3];
    const void*  nrm  = (n_in > 4) ? d_in[4] : nullptr;
    float* out = (float*)d_out;

    k_partial<<<BZ * NN, 128>>>(feat, geo);
    k_middle<<<BZ, 512>>>(W1, W2);
    k_expand<<<BZ * NN, 256>>>(geo, out, nrm);
}

// round 5
// speedup vs baseline: 1.3024x; 1.0579x over previous
#include <cuda_runtime.h>
#include <cuda_bf16.h>
#include <cstdint>

// Problem shapes (fixed by setup_inputs): B=4, N=128, C_IN=C_OUT=32, X=3.
#define BZ 4
#define NN 128
#define CC 32

// ---------------------------------------------------------------------------
// Scratch (no allocations allowed -> __device__ globals)
// ---------------------------------------------------------------------------
// Per-(z,c) partial moments, float4-aligned: [z][c][m][k] with m in 0..15:
//   m=0: p0; m=1..3: p1[x]; m=4..6: gy[y]*p0; m=7..15: gy[y]*p1[x] (7+y*3+x)
__device__ float4 g_partial[BZ][NN][128];     // 1 MB, 16B-aligned
__device__ float  g_U[BZ][512];               // U0[32] | U1[96] | U2[96] | U3[288]

// Robust scalar load: handles int32 or float32 encodings of n_norm.
__device__ __forceinline__ float load_scalar_f(const void* p) {
    int iv = *(const int*)p;
    int ex = (iv >> 23) & 0xFF;
    if (ex > 60 && ex < 200) return __int_as_float(iv);
    return (float)iv;
}

// ---------------------------------------------------------------------------
// K1: per-(z,c) partial moments. grid = B*N blocks, 128 threads.
// Vectorized: 8 independent float4 loads per thread (512B/warp access).
// ---------------------------------------------------------------------------
__global__ void __launch_bounds__(128) k_partial(const float* __restrict__ feat,
                                                 const float* __restrict__ geo) {
    int zc = blockIdx.x;
    int z = zc >> 7;
    int c = zc & (NN - 1);
    int t = threadIdx.x;        // 128
    int kq   = t & 7;           // which float4 within the 32-float row
    int dgrp = t >> 3;          // 0..15

    __shared__ float  sgeo[3][NN];     // geo[z] transposed: [comp][d]
    __shared__ float4 smq[4][16][8];   // [comp][dgrp][kq], 8 KB
    __shared__ float  red[4][32];      // reduced sums [comp][k]
    __shared__ float  sgy[3];

    for (int idx = t; idx < NN * 3; idx += 128) {
        int d = idx / 3, comp = idx - d * 3;
        sgeo[comp][d] = geo[z * NN * 3 + idx];
    }
    if (t < 3) sgy[t] = geo[(z * NN + c) * 3 + t];
    __syncthreads();

    const float4* f4 = (const float4*)(feat + ((size_t)zc << 12));
    float4 s0 = make_float4(0.f, 0.f, 0.f, 0.f);
    float4 sx = s0, sy = s0, sz2 = s0;

    #pragma unroll
    for (int it = 0; it < 8; it++) {
        int d = dgrp + it * 16;
        float4 f = f4[d * 8 + kq];
        float g0 = sgeo[0][d], g1 = sgeo[1][d], g2 = sgeo[2][d];
        s0.x += f.x;  s0.y += f.y;  s0.z += f.z;  s0.w += f.w;
        sx.x = fmaf(f.x, g0, sx.x);  sx.y = fmaf(f.y, g0, sx.y);
        sx.z = fmaf(f.z, g0, sx.z);  sx.w = fmaf(f.w, g0, sx.w);
        sy.x = fmaf(f.x, g1, sy.x);  sy.y = fmaf(f.y, g1, sy.y);
        sy.z = fmaf(f.z, g1, sy.z);  sy.w = fmaf(f.w, g1, sy.w);
        sz2.x = fmaf(f.x, g2, sz2.x);  sz2.y = fmaf(f.y, g2, sz2.y);
        sz2.z = fmaf(f.z, g2, sz2.z);  sz2.w = fmaf(f.w, g2, sz2.w);
    }

    smq[0][dgrp][kq] = s0;
    smq[1][dgrp][kq] = sx;
    smq[2][dgrp][kq] = sy;
    smq[3][dgrp][kq] = sz2;
    __syncthreads();

    // Reduce over 16 dgrps: thread t -> (comp = t>>5, k = t&31).
    {
        int comp = t >> 5;
        int k = t & 31;
        const float* p = (const float*)&smq[comp][0][0];  // 512 floats
        float s = 0.f;
        #pragma unroll
        for (int dg = 0; dg < 16; dg++) s += p[dg * 32 + k];
        red[comp][k] = s;
    }
    __syncthreads();

    // Write 16 moment rows as float4: thread t -> (m = t>>3, kq).
    {
        int m = t >> 3;
        float4 v;
        float* vp = (float*)&v;
        #pragma unroll
        for (int kc = 0; kc < 4; kc++) {
            int k = kq * 4 + kc;
            float r;
            if (m == 0)      r = red[0][k];
            else if (m < 4)  r = red[m][k];
            else if (m < 7)  r = sgy[m - 4] * red[0][k];
            else {
                int mm = m - 7;
                int yy = mm / 3, xx = mm - yy * 3;
                r = sgy[yy] * red[1 + xx][k];
            }
            vp[kc] = r;
        }
        g_partial[z][c][m * 8 + kq] = v;
    }
}

// ---------------------------------------------------------------------------
// K2 (fused middle): per-z block does
//   (1) reduce g_partial over c -> sM[16][32]
//   (2) W12[y,x,i,k] = sum_j W2[y,i,j]*W1[x,j,k] -> shared (36 KB)
//   (3) U coefficients from shared
// grid = B, 512 threads.
// ---------------------------------------------------------------------------
__global__ void __launch_bounds__(512, 1) k_middle(const float* __restrict__ W1,
                                                   const float* __restrict__ W2) {
    int z = blockIdx.x;
    int t = threadIdx.x;  // 512

    __shared__ float sW12[9 * 32 * 32];  // 36 KB: [yx][i][k]
    __shared__ float sM[16][32];         // 2 KB

    // (1) reduce partials over c.
    {
        const float* base = (const float*)&g_partial[z][0][0];
        float s = 0.f;
        #pragma unroll 8
        for (int c = 0; c < NN; c++) s += base[c * 512 + t];
        (&sM[0][0])[t] = s;
    }

    // (2) W12 into shared: 9216 outputs, 18 per thread. Outer loop NOT unrolled.
    for (int r = 0; r < 18; r++) {
        int idx = t + r * 512;
        int yx = idx >> 10;
        int i  = (idx >> 5) & 31;
        int k  = idx & 31;
        int y = yx / 3, x = yx - y * 3;
        const float* w2r = W2 + (y * 32 + i) * 32;
        const float* w1c = W1 + x * 1024 + k;
        float acc = 0.f;
        #pragma unroll
        for (int j = 0; j < 32; j++) acc = fmaf(w2r[j], w1c[j * 32], acc);
        sW12[idx] = acc;
    }
    __syncthreads();

    // (3) U from shared. One output per thread.
    float r = 0.f;
    if (t < 32) {
        int i = t;
        for (int yx = 0; yx < 9; yx++) {
            const float* w = &sW12[(yx * 32 + i) * 32];
            const float* m = &sM[7 + yx][0];
            #pragma unroll
            for (int k = 0; k < 32; k++) r = fmaf(w[k], m[k], r);
        }
    } else if (t < 128) {
        int x = (t - 32) >> 5, i = t & 31;
        for (int y = 0; y < 3; y++) {
            const float* w = &sW12[((y * 3 + x) * 32 + i) * 32];
            const float* m = &sM[4 + y][0];
            #pragma unroll
            for (int k = 0; k < 32; k++) r = fmaf(w[k], m[k], r);
        }
    } else if (t < 224) {
        int y = (t - 128) >> 5, i = t & 31;
        for (int x = 0; x < 3; x++) {
            const float* w = &sW12[((y * 3 + x) * 32 + i) * 32];
            const float* m = &sM[1 + x][0];
            #pragma unroll
            for (int k = 0; k < 32; k++) r = fmaf(w[k], m[k], r);
        }
    } else {
        int m3 = t - 224;
        int yx = m3 >> 5, i = m3 & 31;
        const float* w = &sW12[(yx * 32 + i) * 32];
        const float* m = &sM[0][0];
        #pragma unroll
        for (int k = 0; k < 32; k++) r = fmaf(w[k], m[k], r);
    }
    g_U[z][t] = r;
}

// ---------------------------------------------------------------------------
// K3: output expansion. grid = B*N (one block per (z,a)), 256 threads.
// out[z,a,b,i] = V0[i] + sum_x gb_x * V1[x,i]   (V pre-scaled by 1/n)
//   V0[i]   = inv_n * ( U0[i] - ga . U2[:,i] )
//   V1[x,i] = inv_n * ( -U1[x,i] + sum_y ga_y * U3[y,x,i] )
// Vectorized float4 stores.
// ---------------------------------------------------------------------------
__global__ void __launch_bounds__(256) k_expand(const float* __restrict__ geo,
                                                float* __restrict__ out,
                                                const void* __restrict__ n_norm_ptr) {
    int za = blockIdx.x;
    int z = za >> 7;
    int a = za & (NN - 1);
    int t = threadIdx.x;  // 256

    __shared__ float  sU[512];
    __shared__ float  sg[NN * 3];
    __shared__ float4 V0q[8];        // V0[32]
    __shared__ float4 V1q[3][8];     // V1[3][32]

    sU[t] = g_U[z][t];
    sU[t + 256] = g_U[z][t + 256];
    for (int idx = t; idx < NN * 3; idx += 256) sg[idx] = geo[z * NN * 3 + idx];
    __syncthreads();

    float inv_n = 1.0f / load_scalar_f(n_norm_ptr);
    float ga0 = sg[a * 3 + 0], ga1 = sg[a * 3 + 1], ga2 = sg[a * 3 + 2];

    if (t < 32) {
        int i = t;
        ((float*)V0q)[i] = inv_n *
            (sU[i] - (ga0 * sU[128 + i] + ga1 * sU[160 + i] + ga2 * sU[192 + i]));
    } else if (t < 128) {
        int x = (t - 32) >> 5, i = t & 31;
        ((float*)V1q)[x * 32 + i] = inv_n *
            (-sU[32 + x * 32 + i]
             + ga0 * sU[224 + (0 * 3 + x) * 32 + i]
             + ga1 * sU[224 + (1 * 3 + x) * 32 + i]
             + ga2 * sU[224 + (2 * 3 + x) * 32 + i]);
    }
    __syncthreads();

    int i4   = t & 7;    // which float4 of the 32-float output row
    int bgrp = t >> 3;   // 0..31

    float4 v0  = V0q[i4];
    float4 v10 = V1q[0][i4], v11 = V1q[1][i4], v12 = V1q[2][i4];

    float4* ob4 = (float4*)(out + ((size_t)za << 12));
    #pragma unroll
    for (int it = 0; it < 4; it++) {
        int b = bgrp + it * 32;
        float gb0 = sg[b * 3 + 0], gb1 = sg[b * 3 + 1], gb2 = sg[b * 3 + 2];
        float4 v;
        v.x = fmaf(gb2, v12.x, fmaf(gb1, v11.x, fmaf(gb0, v10.x, v0.x)));
        v.y = fmaf(gb2, v12.y, fmaf(gb1, v11.y, fmaf(gb0, v10.y, v0.y)));
        v.z = fmaf(gb2, v12.z, fmaf(gb1, v11.z, fmaf(gb0, v10.z, v0.z)));
        v.w = fmaf(gb2, v12.w, fmaf(gb1, v11.w, fmaf(gb0, v10.w, v0.w)));
        ob4[b * 8 + i4] = v;
    }
}

// ---------------------------------------------------------------------------
// kernel_launch
// Inputs: features f32[4,128,128,32], geometry f32[4,128,3],
//         W1 f32[3,32,32], W2 f32[3,32,32], n_norm scalar.
// Output: f32[4,128,128,32].
// ---------------------------------------------------------------------------
extern "C" void kernel_launch(void* const* d_in, const int* in_sizes, int n_in,
                              void* d_out, int out_size) {
    const float* feat = (const float*)d_in[0];
    const float* geo  = (const float*)d_in[1];
    const float* W1   = (const float*)d_in[2];
    const float* W2   = (const float*)d_in[3];
    const void*  nrm  = (n_in > 4) ? d_in[4] : nullptr;
    float* out = (float*)d_out;

    k_partial<<<BZ * NN, 128>>>(feat, geo);
    k_middle<<<BZ, 512>>>(W1, W2);
    k_expand<<<BZ * NN, 256>>>(geo, out, nrm);
}

// round 7
// speedup vs baseline: 1.4760x; 1.1333x over previous
#include <cuda_runtime.h>
#include <cuda_bf16.h>
#include <cstdint>

// Problem shapes (fixed by setup_inputs): B=4, N=128, C_IN=C_OUT=32, X=3.
#define BZ 4
#define NN 128
#define CC 32

// ---------------------------------------------------------------------------
// Scratch (no allocations allowed -> __device__ globals)
// ---------------------------------------------------------------------------
// Per-(z,c) BASE sums only (gy factors applied later in k_middle):
//   row = 128 floats: [b][k], b=0: p0 = sum_d f ; b=1..3: p1[x] = sum_d g[d,x]*f
__device__ float4 g_base[BZ][NN][32];         // 256 KB
__device__ float  g_U[BZ][512];               // U0[32] | U1[96] | U2[96] | U3[288]

// Robust scalar load: handles int32 or float32 encodings of n_norm.
__device__ __forceinline__ float load_scalar_f(const void* p) {
    int iv = *(const int*)p;
    int ex = (iv >> 23) & 0xFF;
    if (ex > 60 && ex < 200) return __int_as_float(iv);
    return (float)iv;
}

// ---------------------------------------------------------------------------
// K1: per-(z,c) base sums. grid = B*N blocks, 256 threads.
// Each thread: 4 independent float4 loads.
// ---------------------------------------------------------------------------
__global__ void __launch_bounds__(256) k_partial(const float* __restrict__ feat,
                                                 const float* __restrict__ geo) {
    int zc = blockIdx.x;
    int z = zc >> 7;
    int t = threadIdx.x;        // 256
    int kq   = t & 7;           // which float4 within the 32-float k-row
    int dgrp = t >> 3;          // 0..31

    __shared__ float  sgeo[3][NN];     // geo[z] transposed: [comp][d]
    __shared__ float4 smq[4][32][8];   // [comp][dgrp][kq], 16 KB
    __shared__ float  red[4][32];      // reduced sums [comp][k]

    if (t < NN * 3) {
        int d = t / 3, comp = t - d * 3;
        sgeo[comp][d] = geo[z * NN * 3 + t];
    }
    if (t + 256 < NN * 3) {
        int idx = t + 256;
        int d = idx / 3, comp = idx - d * 3;
        sgeo[comp][d] = geo[z * NN * 3 + idx];
    }
    __syncthreads();

    const float4* f4 = (const float4*)(feat + ((size_t)zc << 12));
    float4 s0 = make_float4(0.f, 0.f, 0.f, 0.f);
    float4 sx = s0, sy = s0, sz2 = s0;

    #pragma unroll
    for (int it = 0; it < 4; it++) {
        int d = dgrp + it * 32;
        float4 f = f4[d * 8 + kq];
        float g0 = sgeo[0][d], g1 = sgeo[1][d], g2 = sgeo[2][d];
        s0.x += f.x;  s0.y += f.y;  s0.z += f.z;  s0.w += f.w;
        sx.x = fmaf(f.x, g0, sx.x);  sx.y = fmaf(f.y, g0, sx.y);
        sx.z = fmaf(f.z, g0, sx.z);  sx.w = fmaf(f.w, g0, sx.w);
        sy.x = fmaf(f.x, g1, sy.x);  sy.y = fmaf(f.y, g1, sy.y);
        sy.z = fmaf(f.z, g1, sy.z);  sy.w = fmaf(f.w, g1, sy.w);
        sz2.x = fmaf(f.x, g2, sz2.x);  sz2.y = fmaf(f.y, g2, sz2.y);
        sz2.z = fmaf(f.z, g2, sz2.z);  sz2.w = fmaf(f.w, g2, sz2.w);
    }

    smq[0][dgrp][kq] = s0;
    smq[1][dgrp][kq] = sx;
    smq[2][dgrp][kq] = sy;
    smq[3][dgrp][kq] = sz2;
    __syncthreads();

    // Reduce over 32 dgrps: threads t<128 -> (comp = t>>5, k = t&31).
    if (t < 128) {
        int comp = t >> 5;
        int k = t & 31;
        const float* p = (const float*)&smq[comp][0][0];  // 1024 floats
        float s = 0.f;
        #pragma unroll
        for (int dg = 0; dg < 32; dg++) s += p[dg * 32 + k];
        red[comp][k] = s;
    }
    __syncthreads();

    // Write the 128-float base row as 32 float4s (coalesced 512B).
    if (t < 32) {
        int c = zc & (NN - 1);
        g_base[z][c][t] = ((const float4*)red)[t];
    }
}

// ---------------------------------------------------------------------------
// K2 (fused middle): per-z block does
//   (1) M[16][32] reduce over c from g_base (gy factors applied here)
//   (2) W12[y,x,i,k] = sum_j W2[y,i,j]*W1[x,j,k] -> shared (36 KB)
//   (3) U coefficients from shared
// grid = B, 512 threads.
//   M rows: m=0: p0; m=1..3: p1[x]; m=4..6: gy[y]*p0; m=7..15: gy[y]*p1[x]
// ---------------------------------------------------------------------------
__global__ void __launch_bounds__(512, 1) k_middle(const float* __restrict__ W1,
                                                   const float* __restrict__ W2,
                                                   const float* __restrict__ geo) {
    int z = blockIdx.x;
    int t = threadIdx.x;  // 512

    __shared__ float sW12[9 * 32 * 32];  // 36 KB: [yx][i][k]
    __shared__ float sM[16][32];         // 2 KB
    __shared__ float sgeo[3][NN];        // 1.5 KB

    if (t < NN * 3) {
        int c = t / 3, comp = t - c * 3;
        sgeo[comp][c] = geo[z * NN * 3 + t];
    }
    __syncthreads();

    // (1) gy-weighted reduce over c. One (m,k) slot per thread (t<512).
    {
        int m = t >> 5;
        int k = t & 31;
        int b, y;
        if (m < 4)      { b = m;               y = -1; }
        else if (m < 7) { b = 0;               y = m - 4; }
        else            { int mm = m - 7; y = mm / 3; b = 1 + (mm - y * 3); }

        const float* base = (const float*)&g_base[z][0][0] + b * 32 + k;  // stride 128
        float s = 0.f;
        if (y < 0) {
            #pragma unroll 16
            for (int c = 0; c < NN; c++) s += base[c * 128];
        } else {
            const float* gy = &sgeo[y][0];
            #pragma unroll 16
            for (int c = 0; c < NN; c++) s = fmaf(base[c * 128], gy[c], s);
        }
        (&sM[0][0])[t] = s;
    }

    // (2) W12 into shared: 9216 outputs, 18 per thread. Outer loop NOT unrolled.
    for (int r = 0; r < 18; r++) {
        int idx = t + r * 512;
        int yx = idx >> 10;
        int i  = (idx >> 5) & 31;
        int k  = idx & 31;
        int y = yx / 3, x = yx - y * 3;
        const float* w2r = W2 + (y * 32 + i) * 32;
        const float* w1c = W1 + x * 1024 + k;
        float acc = 0.f;
        #pragma unroll
        for (int j = 0; j < 32; j++) acc = fmaf(w2r[j], w1c[j * 32], acc);
        sW12[idx] = acc;
    }
    __syncthreads();

    // (3) U from shared. One output per thread.
    float r = 0.f;
    if (t < 32) {
        int i = t;
        for (int yx = 0; yx < 9; yx++) {
            const float* w = &sW12[(yx * 32 + i) * 32];
            const float* m = &sM[7 + yx][0];
            #pragma unroll
            for (int k = 0; k < 32; k++) r = fmaf(w[k], m[k], r);
        }
    } else if (t < 128) {
        int x = (t - 32) >> 5, i = t & 31;
        for (int y = 0; y < 3; y++) {
            const float* w = &sW12[((y * 3 + x) * 32 + i) * 32];
            const float* m = &sM[4 + y][0];
            #pragma unroll
            for (int k = 0; k < 32; k++) r = fmaf(w[k], m[k], r);
        }
    } else if (t < 224) {
        int y = (t - 128) >> 5, i = t & 31;
        for (int x = 0; x < 3; x++) {
            const float* w = &sW12[((y * 3 + x) * 32 + i) * 32];
            const float* m = &sM[1 + x][0];
            #pragma unroll
            for (int k = 0; k < 32; k++) r = fmaf(w[k], m[k], r);
        }
    } else {
        int m3 = t - 224;
        int yx = m3 >> 5, i = m3 & 31;
        const float* w = &sW12[(yx * 32 + i) * 32];
        const float* m = &sM[0][0];
        #pragma unroll
        for (int k = 0; k < 32; k++) r = fmaf(w[k], m[k], r);
    }
    g_U[z][t] = r;
}

// ---------------------------------------------------------------------------
// K3: output expansion. grid = B*N (one block per (z,a)), 256 threads.
// out[z,a,b,i] = V0[i] + sum_x gb_x * V1[x,i]   (V pre-scaled by 1/n)
// ---------------------------------------------------------------------------
__global__ void __launch_bounds__(256) k_expand(const float* __restrict__ geo,
                                                float* __restrict__ out,
                                                const void* __restrict__ n_norm_ptr) {
    int za = blockIdx.x;
    int z = za >> 7;
    int a = za & (NN - 1);
    int t = threadIdx.x;  // 256

    __shared__ float  sU[512];
    __shared__ float  sg[NN * 3];
    __shared__ float4 V0q[8];        // V0[32]
    __shared__ float4 V1q[3][8];     // V1[3][32]

    sU[t] = g_U[z][t];
    sU[t + 256] = g_U[z][t + 256];
    for (int idx = t; idx < NN * 3; idx += 256) sg[idx] = geo[z * NN * 3 + idx];
    __syncthreads();

    float inv_n = 1.0f / load_scalar_f(n_norm_ptr);
    float ga0 = sg[a * 3 + 0], ga1 = sg[a * 3 + 1], ga2 = sg[a * 3 + 2];

    if (t < 32) {
        int i = t;
        ((float*)V0q)[i] = inv_n *
            (sU[i] - (ga0 * sU[128 + i] + ga1 * sU[160 + i] + ga2 * sU[192 + i]));
    } else if (t < 128) {
        int x = (t - 32) >> 5, i = t & 31;
        ((float*)V1q)[x * 32 + i] = inv_n *
            (-sU[32 + x * 32 + i]
             + ga0 * sU[224 + (0 * 3 + x) * 32 + i]
             + ga1 * sU[224 + (1 * 3 + x) * 32 + i]
             + ga2 * sU[224 + (2 * 3 + x) * 32 + i]);
    }
    __syncthreads();

    int i4   = t & 7;    // which float4 of the 32-float output row
    int bgrp = t >> 3;   // 0..31

    float4 v0  = V0q[i4];
    float4 v10 = V1q[0][i4], v11 = V1q[1][i4], v12 = V1q[2][i4];

    float4* ob4 = (float4*)(out + ((size_t)za << 12));
    #pragma unroll
    for (int it = 0; it < 4; it++) {
        int b = bgrp + it * 32;
        float gb0 = sg[b * 3 + 0], gb1 = sg[b * 3 + 1], gb2 = sg[b * 3 + 2];
        float4 v;
        v.x = fmaf(gb2, v12.x, fmaf(gb1, v11.x, fmaf(gb0, v10.x, v0.x)));
        v.y = fmaf(gb2, v12.y, fmaf(gb1, v11.y, fmaf(gb0, v10.y, v0.y)));
        v.z = fmaf(gb2, v12.z, fmaf(gb1, v11.z, fmaf(gb0, v10.z, v0.z)));
        v.w = fmaf(gb2, v12.w, fmaf(gb1, v11.w, fmaf(gb0, v10.w, v0.w)));
        ob4[b * 8 + i4] = v;
    }
}

// ---------------------------------------------------------------------------
// kernel_launch
// Inputs: features f32[4,128,128,32], geometry f32[4,128,3],
//         W1 f32[3,32,32], W2 f32[3,32,32], n_norm scalar.
// Output: f32[4,128,128,32].
// ---------------------------------------------------------------------------
extern "C" void kernel_launch(void* const* d_in, const int* in_sizes, int n_in,
                              void* d_out, int out_size) {
    const float* feat = (const float*)d_in[0];
    const float* geo  = (const float*)d_in[1];
    const float* W1   = (const float*)d_in[2];
    const float* W2   = (const float*)d_in[3];
    const void*  nrm  = (n_in > 4) ? d_in[4] : nullptr;
    float* out = (float*)d_out;

    k_partial<<<BZ * NN, 256>>>(feat, geo);
    k_middle<<<BZ, 512>>>(W1, W2, geo);
    k_expand<<<BZ * NN, 256>>>(geo, out, nrm);
}